// round 2
// baseline (speedup 1.0000x reference)
#include <cuda_runtime.h>
#include <cstdint>

#define NPTS   32768
#define NBATCH 4
#define MPER   8192
#define KNN    8
#define HDIM   128
#define COMB   72            // (K+1)*C_IN
#define TABSZ  (4*64*64*64)  // direct-mapped voxel key table

// ---------------- scratch (device globals; no allocations allowed) ----------
__device__ int   g_table[TABSZ];
__device__ int   g_nbr[NPTS * KNN];
__device__ float g_pre1[NPTS * HDIM];
__device__ float g_h[NPTS * HDIM];
__device__ float g_pre2[NPTS * HDIM];
__device__ float g_part[2 * 256 * HDIM];
__device__ float g_stats1[2 * HDIM];   // scale, shift
__device__ float g_stats2[2 * HDIM];

// ---------------- init table ------------------------------------------------
__global__ void k_init() {
    int i = blockIdx.x * 256 + threadIdx.x;
    g_table[i] = -1;
}

// ---------------- build hash (direct) table ---------------------------------
__global__ void k_build(const int* __restrict__ coords) {
    int n = blockIdx.x * 256 + threadIdx.x;
    int4 c = ((const int4*)coords)[n];
    int key = ((c.x * 64 + c.y + 1) * 64 + (c.z + 1)) * 64 + (c.w + 1);
    g_table[key] = n;
}

// ---------------- brute-force per-batch kNN (exact jax top_k order) ---------
__global__ void k_knn(const int* __restrict__ coords) {
    __shared__ int pc[MPER];            // packed coords, 32 KB
    int b    = blockIdx.x >> 5;         // 32 blocks / batch
    int qi   = ((blockIdx.x & 31) << 8) + threadIdx.x;
    int base = b * MPER;
    for (int i = threadIdx.x; i < MPER; i += 256) {
        const int* c = coords + (size_t)(base + i) * 4;
        pc[i] = c[1] | (c[2] << 8) | (c[3] << 16);
    }
    __syncthreads();

    unsigned q = (unsigned)pc[qi];
    unsigned best[8];
#pragma unroll
    for (int s = 0; s < 8; s++) best[s] = 0xFFFFFFFFu;

#pragma unroll 4
    for (int i = 0; i < MPER; i++) {
        unsigned ad = __vabsdiffu4(q, (unsigned)pc[i]);
        unsigned d2 = __dp4a(ad, ad, 0u);
        unsigned key = (d2 << 13) | (unsigned)i;  // d2<4096, i<8192: exact stable order
        if (key < best[7]) {
#pragma unroll
            for (int s = 0; s < 8; s++) {
                unsigned mx = key > best[s] ? key : best[s];
                best[s]     = key < best[s] ? key : best[s];
                key = mx;
            }
        }
    }
    int n = base + qi;
#pragma unroll
    for (int s = 0; s < 8; s++)
        g_nbr[n * 8 + s] = base + (int)(best[s] & 0x1FFFu);
}

// ---------------- GEMM1: combined[N,72] @ w1[72,128] -> pre1 ----------------
__global__ void k_gemm1(const float* __restrict__ feats, const float* __restrict__ w1) {
    __shared__ float w_s[COMB * HDIM];  // 36 KB
    __shared__ float c_s[32 * COMB];    // 9 KB
    int base = blockIdx.x * 32;
    for (int i = threadIdx.x; i < COMB * HDIM; i += 128) w_s[i] = w1[i];
    for (int idx = threadIdx.x; idx < 32 * 9; idx += 128) {
        int p = idx / 9, slot = idx - p * 9;
        int src = (slot == 0) ? (base + p) : g_nbr[(base + p) * 8 + slot - 1];
        const float4* s4 = (const float4*)(feats + (size_t)src * 8);
        float4* dst = (float4*)&c_s[p * COMB + slot * 8];
        dst[0] = s4[0]; dst[1] = s4[1];
    }
    __syncthreads();
    int ch = threadIdx.x;
    for (int p = 0; p < 32; p++) {
        float acc = 0.f;
#pragma unroll 8
        for (int k = 0; k < COMB; k++)
            acc += c_s[p * COMB + k] * w_s[k * HDIM + ch];
        g_pre1[(size_t)(base + p) * HDIM + ch] = acc;
    }
}

// ---------------- BN partial sums (two-pass, deterministic) -----------------
__global__ void k_bnstats(int which) {
    const float* buf = which ? g_pre2 : g_pre1;
    int ch = threadIdx.x;
    float s = 0.f, q = 0.f;
    const float* p = buf + (size_t)blockIdx.x * 128 * HDIM + ch;
#pragma unroll 4
    for (int r = 0; r < 128; r++) {
        float v = p[r * HDIM];
        s += v; q += v * v;
    }
    g_part[blockIdx.x * HDIM + ch] = s;
    g_part[256 * HDIM + blockIdx.x * HDIM + ch] = q;
}

__global__ void k_bnfin(const float* __restrict__ gamma, const float* __restrict__ beta,
                        int which) {
    int ch = threadIdx.x;
    float s = 0.f, q = 0.f;
#pragma unroll 8
    for (int i = 0; i < 256; i++) {
        s += g_part[i * HDIM + ch];
        q += g_part[256 * HDIM + i * HDIM + ch];
    }
    float mu  = s * (1.f / NPTS);
    float var = q * (1.f / NPTS) - mu * mu;
    float sc  = rsqrtf(var + 1e-5f) * gamma[ch];
    float* st = which ? g_stats2 : g_stats1;
    st[ch]        = sc;
    st[HDIM + ch] = beta[ch] - mu * sc;
}

// ---------------- apply BN1 + ReLU -> h -------------------------------------
__global__ void k_happly() {
    int i = blockIdx.x * 256 + threadIdx.x;       // float4 units: NPTS*32
    float4 v = ((const float4*)g_pre1)[i];
    int c = (i & 31) << 2;
    float s0 = g_stats1[c],     s1 = g_stats1[c + 1];
    float s2 = g_stats1[c + 2], s3 = g_stats1[c + 3];
    float h0 = g_stats1[HDIM + c],     h1 = g_stats1[HDIM + c + 1];
    float h2 = g_stats1[HDIM + c + 2], h3 = g_stats1[HDIM + c + 3];
    v.x = fmaxf(v.x * s0 + h0, 0.f);
    v.y = fmaxf(v.y * s1 + h1, 0.f);
    v.z = fmaxf(v.z * s2 + h2, 0.f);
    v.w = fmaxf(v.w * s3 + h3, 0.f);
    ((float4*)g_h)[i] = v;
}

// ---------------- sparse 3^3 conv: pre2[n] = sum_o h[j(n,o)] @ w3[o] --------
// TILE = 64 points/block, 256 threads, micro-tile 4x8 per thread.
#define CONV_SMEM ((128*128 + 64*128) * 4 + 27*64*4)
__global__ void __launch_bounds__(256, 2)
k_conv(const int* __restrict__ coords, const float* __restrict__ w3) {
    extern __shared__ float sm[];
    float* w_sm = sm;                         // 128*128
    float* g_sm = sm + 128 * 128;             // 64*128
    int*   j_s  = (int*)(sm + 128 * 128 + 64 * 128);  // 27*64
    int base = blockIdx.x * 64;

    for (int idx = threadIdx.x; idx < 27 * 64; idx += 256) {
        int o = idx >> 6, p = idx & 63;
        int4 c = ((const int4*)coords)[base + p];
        int ox = o / 9 - 1;
        int oy = (o / 3) % 3 - 1;
        int oz = o % 3 - 1;
        int key = ((c.x * 64 + c.y + 1 + ox) * 64 + (c.z + 1 + oy)) * 64 + (c.w + 1 + oz);
        j_s[idx] = g_table[key];
    }

    float acc[4][8];
#pragma unroll
    for (int i = 0; i < 4; i++)
#pragma unroll
        for (int j = 0; j < 8; j++) acc[i][j] = 0.f;

    int p0 = (threadIdx.x >> 4) * 4;
    int c0 = (threadIdx.x & 15) * 8;

    for (int o = 0; o < 27; o++) {
        __syncthreads();
        // load w3[o] (64 KB) into smem
        const float4* ws = (const float4*)(w3 + (size_t)o * 128 * 128);
#pragma unroll
        for (int t = 0; t < 16; t++)
            ((float4*)w_sm)[threadIdx.x + t * 256] = ws[threadIdx.x + t * 256];
        // gather 64 rows of h (zero when invalid)
#pragma unroll
        for (int t = 0; t < 8; t++) {
            int i = threadIdx.x + t * 256;
            int p = i >> 5, u = i & 31;
            int j = j_s[(o << 6) + p];
            float4 v = make_float4(0.f, 0.f, 0.f, 0.f);
            if (j >= 0) v = ((const float4*)g_h)[(size_t)j * 32 + u];
            ((float4*)g_sm)[i] = v;
        }
        __syncthreads();
#pragma unroll 2
        for (int k = 0; k < 128; k++) {
            float4 wa = *(const float4*)(w_sm + k * 128 + c0);
            float4 wb = *(const float4*)(w_sm + k * 128 + c0 + 4);
            float gv[4];
#pragma unroll
            for (int i = 0; i < 4; i++) gv[i] = g_sm[(p0 + i) * 128 + k];
#pragma unroll
            for (int i = 0; i < 4; i++) {
                acc[i][0] += gv[i] * wa.x; acc[i][1] += gv[i] * wa.y;
                acc[i][2] += gv[i] * wa.z; acc[i][3] += gv[i] * wa.w;
                acc[i][4] += gv[i] * wb.x; acc[i][5] += gv[i] * wb.y;
                acc[i][6] += gv[i] * wb.z; acc[i][7] += gv[i] * wb.w;
            }
        }
    }
#pragma unroll
    for (int i = 0; i < 4; i++) {
        float4 a = make_float4(acc[i][0], acc[i][1], acc[i][2], acc[i][3]);
        float4 b = make_float4(acc[i][4], acc[i][5], acc[i][6], acc[i][7]);
        float4* dst = (float4*)(g_pre2 + (size_t)(base + p0 + i) * HDIM + c0);
        dst[0] = a; dst[1] = b;
    }
}

// ---------------- final: out = relu(bn2(pre2)) @ w_out[128,16] --------------
__global__ void k_final(const float* __restrict__ w_out, float* __restrict__ out) {
    __shared__ float h_s[16 * HDIM];   // 8 KB
    __shared__ float w_s[HDIM * 16];   // 8 KB
    int base = blockIdx.x * 16;
    for (int i = threadIdx.x; i < HDIM * 16; i += 256) w_s[i] = w_out[i];
    for (int i = threadIdx.x; i < 16 * HDIM; i += 256) {
        int ch = i & 127;
        float v = g_pre2[(size_t)base * HDIM + i];
        v = v * g_stats2[ch] + g_stats2[HDIM + ch];
        h_s[i] = fmaxf(v, 0.f);
    }
    __syncthreads();
    int p = threadIdx.x >> 4, oc = threadIdx.x & 15;
    float acc = 0.f;
#pragma unroll 8
    for (int k = 0; k < HDIM; k++)
        acc += h_s[p * HDIM + k] * w_s[k * 16 + oc];
    out[(size_t)(base + p) * 16 + oc] = acc;
}

// ---------------- launcher ---------------------------------------------------
extern "C" void kernel_launch(void* const* d_in, const int* in_sizes, int n_in,
                              void* d_out, int out_size) {
    const int*   coords = (const int*)  d_in[0];
    const float* feats  = (const float*)d_in[1];
    const float* w1     = (const float*)d_in[2];
    const float* g1     = (const float*)d_in[3];
    const float* b1     = (const float*)d_in[4];
    const float* w3     = (const float*)d_in[5];
    const float* g2     = (const float*)d_in[6];
    const float* b2     = (const float*)d_in[7];
    const float* w_out  = (const float*)d_in[8];
    float* out = (float*)d_out;

    cudaFuncSetAttribute(k_conv, cudaFuncAttributeMaxDynamicSharedMemorySize, CONV_SMEM);

    k_init   <<<TABSZ / 256, 256>>>();
    k_build  <<<NPTS / 256, 256>>>(coords);
    k_knn    <<<128, 256>>>(coords);
    k_gemm1  <<<NPTS / 32, 128>>>(feats, w1);
    k_bnstats<<<256, 128>>>(0);
    k_bnfin  <<<1, 128>>>(g1, b1, 0);
    k_happly <<<NPTS * 32 / 256, 256>>>();
    k_conv   <<<NPTS / 64, 256, CONV_SMEM>>>(coords, w3);
    k_bnstats<<<256, 128>>>(1);
    k_bnfin  <<<1, 128>>>(g2, b2, 1);
    k_final  <<<NPTS / 16, 256>>>(w_out, out);
}

// round 4
// speedup vs baseline: 2.3919x; 2.3919x over previous
#include <cuda_runtime.h>
#include <cstdint>

#define NPTS   32768
#define NBATCH 4
#define MPER   8192
#define KNN    8
#define HDIM   128
#define COMB   72            // (K+1)*C_IN
#define TABSZ  (4*64*64*64)  // direct-mapped voxel key table

// ---------------- scratch (device globals; no allocations allowed) ----------
__device__ int   g_table[TABSZ];
__device__ int   g_nbr[NPTS * KNN];
__device__ float g_pre1[NPTS * HDIM];
__device__ float g_h[NPTS * HDIM];
__device__ float g_pre2[NPTS * HDIM];
__device__ float g_part[2 * 256 * HDIM];
__device__ float g_stats1[2 * HDIM];   // scale, shift
__device__ float g_stats2[2 * HDIM];

// ---------------- helpers ----------------------------------------------------
__device__ __forceinline__ unsigned f2tf(float f) {
    unsigned u;
    asm("cvt.rna.tf32.f32 %0, %1;" : "=r"(u) : "f"(f));
    return u;
}

__device__ __forceinline__ void mma_tf32(float* c, const unsigned* a,
                                         unsigned b0, unsigned b1) {
    asm volatile(
        "mma.sync.aligned.m16n8k8.row.col.f32.tf32.tf32.f32 "
        "{%0,%1,%2,%3},{%4,%5,%6,%7},{%8,%9},{%0,%1,%2,%3};"
        : "+f"(c[0]), "+f"(c[1]), "+f"(c[2]), "+f"(c[3])
        : "r"(a[0]), "r"(a[1]), "r"(a[2]), "r"(a[3]), "r"(b0), "r"(b1));
}

// ---------------- init table ------------------------------------------------
__global__ void k_init() {
    int i = blockIdx.x * 256 + threadIdx.x;
    g_table[i] = -1;
}

// ---------------- build direct table ----------------------------------------
__global__ void k_build(const int* __restrict__ coords) {
    int n = blockIdx.x * 256 + threadIdx.x;
    int4 c = ((const int4*)coords)[n];
    int key = ((c.x * 64 + c.y + 1) * 64 + (c.z + 1)) * 64 + (c.w + 1);
    g_table[key] = n;
}

// ---------------- brute-force per-batch kNN (exact jax top_k order) ---------
__global__ void k_knn(const int* __restrict__ coords) {
    __shared__ int pc[MPER];            // packed coords, 32 KB
    int b    = blockIdx.x >> 5;         // 32 blocks / batch
    int qi   = ((blockIdx.x & 31) << 8) + threadIdx.x;
    int base = b * MPER;
    for (int i = threadIdx.x; i < MPER; i += 256) {
        const int* c = coords + (size_t)(base + i) * 4;
        pc[i] = c[1] | (c[2] << 8) | (c[3] << 16);
    }
    __syncthreads();

    unsigned q = (unsigned)pc[qi];
    unsigned best[8];
#pragma unroll
    for (int s = 0; s < 8; s++) best[s] = 0xFFFFFFFFu;

#pragma unroll 4
    for (int i = 0; i < MPER; i++) {
        unsigned ad = __vabsdiffu4(q, (unsigned)pc[i]);
        unsigned d2 = __dp4a(ad, ad, 0u);
        unsigned key = (d2 << 13) | (unsigned)i;  // d2<4096, i<8192: exact stable order
        if (key < best[7]) {
#pragma unroll
            for (int s = 0; s < 8; s++) {
                unsigned mx = key > best[s] ? key : best[s];
                best[s]     = key < best[s] ? key : best[s];
                key = mx;
            }
        }
    }
    int n = base + qi;
#pragma unroll
    for (int s = 0; s < 8; s++)
        g_nbr[n * 8 + s] = base + (int)(best[s] & 0x1FFFu);
}

// ---------------- GEMM1: combined[N,72] @ w1[72,128] -> pre1 ----------------
__global__ void k_gemm1(const float* __restrict__ feats, const float* __restrict__ w1) {
    __shared__ float c_s[32 * COMB];    // 9 KB
    int base = blockIdx.x * 32;
    int ch = threadIdx.x;               // 128 threads = channels

    for (int idx = threadIdx.x; idx < 32 * 9; idx += 128) {
        int p = idx / 9, slot = idx - p * 9;
        int src = (slot == 0) ? (base + p) : g_nbr[(base + p) * 8 + slot - 1];
        const float4* s4 = (const float4*)(feats + (size_t)src * 8);
        float4* dst = (float4*)&c_s[p * COMB + slot * 8];
        dst[0] = s4[0]; dst[1] = s4[1];
    }

    float wreg[COMB];
#pragma unroll
    for (int k = 0; k < COMB; k++) wreg[k] = w1[k * HDIM + ch];
    __syncthreads();

    for (int p = 0; p < 32; p++) {
        const float4* cp = (const float4*)(c_s + p * COMB);
        float acc = 0.f;
#pragma unroll
        for (int k4 = 0; k4 < COMB / 4; k4++) {
            float4 cv = cp[k4];
            acc += cv.x * wreg[k4 * 4]     + cv.y * wreg[k4 * 4 + 1]
                 + cv.z * wreg[k4 * 4 + 2] + cv.w * wreg[k4 * 4 + 3];
        }
        g_pre1[(size_t)(base + p) * HDIM + ch] = acc;
    }
}

// ---------------- BN partial sums (two-pass, deterministic) -----------------
__global__ void k_bnstats(int which) {
    const float* buf = which ? g_pre2 : g_pre1;
    int ch = threadIdx.x;
    float s = 0.f, q = 0.f;
    const float* p = buf + (size_t)blockIdx.x * 128 * HDIM + ch;
#pragma unroll 4
    for (int r = 0; r < 128; r++) {
        float v = p[r * HDIM];
        s += v; q += v * v;
    }
    g_part[blockIdx.x * HDIM + ch] = s;
    g_part[256 * HDIM + blockIdx.x * HDIM + ch] = q;
}

__global__ void k_bnfin(const float* __restrict__ gamma, const float* __restrict__ beta,
                        int which) {
    int ch = threadIdx.x;
    float s = 0.f, q = 0.f;
#pragma unroll 8
    for (int i = 0; i < 256; i++) {
        s += g_part[i * HDIM + ch];
        q += g_part[256 * HDIM + i * HDIM + ch];
    }
    float mu  = s * (1.f / NPTS);
    float var = q * (1.f / NPTS) - mu * mu;
    float sc  = rsqrtf(var + 1e-5f) * gamma[ch];
    float* st = which ? g_stats2 : g_stats1;
    st[ch]        = sc;
    st[HDIM + ch] = beta[ch] - mu * sc;
}

// ---------------- apply BN1 + ReLU -> h -------------------------------------
__global__ void k_happly() {
    int i = blockIdx.x * 256 + threadIdx.x;       // float4 units: NPTS*32
    float4 v = ((const float4*)g_pre1)[i];
    int c = (i & 31) << 2;
    float s0 = g_stats1[c],     s1 = g_stats1[c + 1];
    float s2 = g_stats1[c + 2], s3 = g_stats1[c + 3];
    float h0 = g_stats1[HDIM + c],     h1 = g_stats1[HDIM + c + 1];
    float h2 = g_stats1[HDIM + c + 2], h3 = g_stats1[HDIM + c + 3];
    v.x = fmaxf(v.x * s0 + h0, 0.f);
    v.y = fmaxf(v.y * s1 + h1, 0.f);
    v.z = fmaxf(v.z * s2 + h2, 0.f);
    v.w = fmaxf(v.w * s3 + h3, 0.f);
    ((float4*)g_h)[i] = v;
}

// ---------------- sparse 3^3 conv via tf32 mma.sync -------------------------
// block = 128 points x 128 out-chans; 8 warps, each m32 x n64; K=128, 27 offsets.
#define GPAD 132   // stride ≡ 4 (mod 32): conflict-free A-fragment loads
#define WPAD 136   // stride ≡ 8 (mod 32): conflict-free B-fragment loads
#define CONV_SMEM (128*GPAD*4 + 128*WPAD*4 + 27*128*4)

__global__ void __launch_bounds__(256, 1)
k_conv(const int* __restrict__ coords, const float* __restrict__ w3) {
    extern __shared__ float sm[];
    float* g_sm = sm;                        // [128][GPAD] gathered h (tf32 bits)
    float* w_sm = sm + 128 * GPAD;           // [128][WPAD] w3[o]     (tf32 bits)
    int*   j_s  = (int*)(sm + 128 * GPAD + 128 * WPAD);  // [27*128]
    int base = blockIdx.x * 128;
    int tid  = threadIdx.x;

    for (int idx = tid; idx < 27 * 128; idx += 256) {
        int o = idx >> 7, p = idx & 127;
        int4 c = ((const int4*)coords)[base + p];
        int ox = o / 9 - 1, oy = (o / 3) % 3 - 1, oz = o % 3 - 1;
        int key = ((c.x * 64 + c.y + 1 + ox) * 64 + (c.z + 1 + oy)) * 64 + (c.w + 1 + oz);
        j_s[idx] = g_table[key];
    }

    int lane = tid & 31, warp = tid >> 5;
    int gid = lane >> 2, tig = lane & 3;
    int mgrp = warp >> 1;                    // 0..3 : 32-point group
    int ngrp = warp & 1;                     // 0..1 : 64-chan group

    float acc[2][8][4];
#pragma unroll
    for (int mt = 0; mt < 2; mt++)
#pragma unroll
        for (int nt = 0; nt < 8; nt++)
#pragma unroll
            for (int r = 0; r < 4; r++) acc[mt][nt][r] = 0.f;

    for (int o = 0; o < 27; o++) {
        __syncthreads();
        // stage w3[o]: 128x128 fp32 -> tf32 bits
        const float4* ws = (const float4*)(w3 + (size_t)o * 16384);
#pragma unroll
        for (int t = 0; t < 16; t++) {
            int i4 = tid + t * 256;
            float4 v = ws[i4];
            int row = i4 >> 5, col4 = i4 & 31;
            float4 u;
            u.x = __uint_as_float(f2tf(v.x));
            u.y = __uint_as_float(f2tf(v.y));
            u.z = __uint_as_float(f2tf(v.z));
            u.w = __uint_as_float(f2tf(v.w));
            *(float4*)&w_sm[row * WPAD + col4 * 4] = u;
        }
        // gather 128 rows of h (zero when invalid) -> tf32 bits
#pragma unroll
        for (int t = 0; t < 16; t++) {
            int i4 = tid + t * 256;
            int p = i4 >> 5, u = i4 & 31;
            int j = j_s[(o << 7) + p];
            float4 v = make_float4(0.f, 0.f, 0.f, 0.f);
            if (j >= 0) v = ((const float4*)g_h)[(size_t)j * 32 + u];
            float4 tv;
            tv.x = __uint_as_float(f2tf(v.x));
            tv.y = __uint_as_float(f2tf(v.y));
            tv.z = __uint_as_float(f2tf(v.z));
            tv.w = __uint_as_float(f2tf(v.w));
            *(float4*)&g_sm[p * GPAD + u * 4] = tv;
        }
        __syncthreads();

#pragma unroll 2
        for (int kt = 0; kt < 16; kt++) {
            int k0 = kt * 8;
            unsigned a[2][4];
#pragma unroll
            for (int mt = 0; mt < 2; mt++) {
                int pr = mgrp * 32 + mt * 16;
                a[mt][0] = __float_as_uint(g_sm[(pr + gid) * GPAD + k0 + tig]);
                a[mt][1] = __float_as_uint(g_sm[(pr + gid + 8) * GPAD + k0 + tig]);
                a[mt][2] = __float_as_uint(g_sm[(pr + gid) * GPAD + k0 + tig + 4]);
                a[mt][3] = __float_as_uint(g_sm[(pr + gid + 8) * GPAD + k0 + tig + 4]);
            }
#pragma unroll
            for (int nt = 0; nt < 8; nt++) {
                int nc = ngrp * 64 + nt * 8;
                unsigned b0 = __float_as_uint(w_sm[(k0 + tig) * WPAD + nc + gid]);
                unsigned b1 = __float_as_uint(w_sm[(k0 + tig + 4) * WPAD + nc + gid]);
                mma_tf32(acc[0][nt], a[0], b0, b1);
                mma_tf32(acc[1][nt], a[1], b0, b1);
            }
        }
    }
    // store accumulators
#pragma unroll
    for (int mt = 0; mt < 2; mt++) {
#pragma unroll
        for (int nt = 0; nt < 8; nt++) {
            int row0 = base + mgrp * 32 + mt * 16 + gid;
            int col  = ngrp * 64 + nt * 8 + tig * 2;
            *(float2*)&g_pre2[(size_t)row0 * HDIM + col] =
                make_float2(acc[mt][nt][0], acc[mt][nt][1]);
            *(float2*)&g_pre2[(size_t)(row0 + 8) * HDIM + col] =
                make_float2(acc[mt][nt][2], acc[mt][nt][3]);
        }
    }
}

// ---------------- final: out = relu(bn2(pre2)) @ w_out[128,16] --------------
__global__ void k_final(const float* __restrict__ w_out, float* __restrict__ out) {
    __shared__ float h_s[16 * HDIM];   // 8 KB
    __shared__ float w_s[HDIM * 16];   // 8 KB
    int base = blockIdx.x * 16;
    for (int i = threadIdx.x; i < HDIM * 16; i += 256) w_s[i] = w_out[i];
    for (int i = threadIdx.x; i < 16 * HDIM; i += 256) {
        int ch = i & 127;
        float v = g_pre2[(size_t)base * HDIM + i];
        v = v * g_stats2[ch] + g_stats2[HDIM + ch];
        h_s[i] = fmaxf(v, 0.f);
    }
    __syncthreads();
    int p = threadIdx.x >> 4, oc = threadIdx.x & 15;
    float acc = 0.f;
#pragma unroll 8
    for (int k = 0; k < HDIM; k++)
        acc += h_s[p * HDIM + k] * w_s[k * 16 + oc];
    out[(size_t)(base + p) * 16 + oc] = acc;
}

// ---------------- launcher ---------------------------------------------------
extern "C" void kernel_launch(void* const* d_in, const int* in_sizes, int n_in,
                              void* d_out, int out_size) {
    const int*   coords = (const int*)  d_in[0];
    const float* feats  = (const float*)d_in[1];
    const float* w1     = (const float*)d_in[2];
    const float* g1     = (const float*)d_in[3];
    const float* b1     = (const float*)d_in[4];
    const float* w3     = (const float*)d_in[5];
    const float* g2     = (const float*)d_in[6];
    const float* b2     = (const float*)d_in[7];
    const float* w_out  = (const float*)d_in[8];
    float* out = (float*)d_out;

    cudaFuncSetAttribute(k_conv, cudaFuncAttributeMaxDynamicSharedMemorySize, CONV_SMEM);

    k_init   <<<TABSZ / 256, 256>>>();
    k_build  <<<NPTS / 256, 256>>>(coords);
    k_knn    <<<128, 256>>>(coords);
    k_gemm1  <<<NPTS / 32, 128>>>(feats, w1);
    k_bnstats<<<256, 128>>>(0);
    k_bnfin  <<<1, 128>>>(g1, b1, 0);
    k_happly <<<NPTS * 32 / 256, 256>>>();
    k_conv   <<<NPTS / 128, 256, CONV_SMEM>>>(coords, w3);
    k_bnstats<<<256, 128>>>(1);
    k_bnfin  <<<1, 128>>>(g2, b2, 1);
    k_final  <<<NPTS / 16, 256>>>(w_out, out);
}

// round 7
// speedup vs baseline: 3.0042x; 1.2560x over previous
#include <cuda_runtime.h>
#include <cstdint>

#define NPTS   32768
#define NBATCH 4
#define MPER   8192
#define KNN    8
#define HDIM   128
#define COMB   72
#define TABSZ  (4*64*64*64)

// ---------------- scratch ----------------------------------------------------
__device__ int      g_table[TABSZ];
__device__ unsigned g_kk[2 * NPTS * KNN];     // per-half sorted top-8 keys
__device__ int      g_nbr[NPTS * KNN];
__device__ float    g_pre1[NPTS * HDIM];
__device__ float    g_h[NPTS * HDIM];         // tf32-rounded bits
__device__ float    g_w3t[27 * HDIM * HDIM];  // tf32-rounded w3
__device__ float    g_pre2[NPTS * HDIM];
#define SQOFF (1024 * HDIM)
__device__ float    g_part[2 * 1024 * HDIM];
__device__ float    g_stats1[2 * HDIM];
__device__ float    g_stats2[2 * HDIM];

// ---------------- helpers ----------------------------------------------------
__device__ __forceinline__ unsigned f2tf(float f) {
    unsigned u;
    asm("cvt.rna.tf32.f32 %0, %1;" : "=r"(u) : "f"(f));
    return u;
}
__device__ __forceinline__ void mma_tf32(float* c, const unsigned* a,
                                         unsigned b0, unsigned b1) {
    asm volatile(
        "mma.sync.aligned.m16n8k8.row.col.f32.tf32.tf32.f32 "
        "{%0,%1,%2,%3},{%4,%5,%6,%7},{%8,%9},{%0,%1,%2,%3};"
        : "+f"(c[0]), "+f"(c[1]), "+f"(c[2]), "+f"(c[3])
        : "r"(a[0]), "r"(a[1]), "r"(a[2]), "r"(a[3]), "r"(b0), "r"(b1));
}
__device__ __forceinline__ void cp16(void* dst, const void* src, int bytes) {
    unsigned d = (unsigned)__cvta_generic_to_shared(dst);
    asm volatile("cp.async.ca.shared.global [%0], [%1], 16, %2;"
                 :: "r"(d), "l"(src), "r"(bytes));
}
__device__ __forceinline__ void cp_commit() {
    asm volatile("cp.async.commit_group;");
}
template <int N> __device__ __forceinline__ void cp_wait() {
    asm volatile("cp.async.wait_group %0;" :: "n"(N));
}

// ---------------- table -------------------------------------------------------
__global__ void k_init() { g_table[blockIdx.x * 256 + threadIdx.x] = -1; }

__global__ void k_build(const int* __restrict__ coords) {
    int n = blockIdx.x * 256 + threadIdx.x;
    int4 c = ((const int4*)coords)[n];
    g_table[((c.x * 64 + c.y + 1) * 64 + (c.z + 1)) * 64 + (c.w + 1)] = n;
}

// ---------------- kNN: 2-way candidate split ---------------------------------
// grid 256: b = bx>>6, half = (bx>>5)&1, qb = bx&31
__global__ void k_knn2(const int* __restrict__ coords) {
    __shared__ int pc[MPER / 2];   // 16 KB
    int b    = blockIdx.x >> 6;
    int half = (blockIdx.x >> 5) & 1;
    int qb   = blockIdx.x & 31;
    int base = b * MPER;
    int cbase = base + half * 4096;
    for (int i = threadIdx.x; i < 4096; i += 256) {
        const int* c = coords + (size_t)(cbase + i) * 4;
        pc[i] = c[1] | (c[2] << 8) | (c[3] << 16);
    }
    int n = base + qb * 256 + threadIdx.x;
    const int* qc = coords + (size_t)n * 4;
    unsigned q = (unsigned)(qc[1] | (qc[2] << 8) | (qc[3] << 16));
    __syncthreads();

    unsigned best[8];
#pragma unroll
    for (int s = 0; s < 8; s++) best[s] = 0xFFFFFFFFu;

    unsigned ioff = half * 4096u;
#pragma unroll 4
    for (int i = 0; i < 4096; i++) {
        unsigned ad = __vabsdiffu4(q, (unsigned)pc[i]);
        unsigned d2 = __dp4a(ad, ad, 0u);
        unsigned key = (d2 << 13) | (ioff + (unsigned)i);
        if (key < best[7]) {
#pragma unroll
            for (int s = 0; s < 8; s++) {
                unsigned mx = key > best[s] ? key : best[s];
                best[s]     = key < best[s] ? key : best[s];
                key = mx;
            }
        }
    }
#pragma unroll
    for (int s = 0; s < 8; s++)
        g_kk[(size_t)half * NPTS * 8 + (size_t)n * 8 + s] = best[s];
}

__global__ void k_kmerge() {
    int n = blockIdx.x * 256 + threadIdx.x;
    unsigned ka[8], kb[8];
    const uint4* pa = (const uint4*)&g_kk[(size_t)n * 8];
    const uint4* pb = (const uint4*)&g_kk[(size_t)NPTS * 8 + (size_t)n * 8];
    uint4 a0 = pa[0], a1 = pa[1], b0 = pb[0], b1 = pb[1];
    ka[0]=a0.x; ka[1]=a0.y; ka[2]=a0.z; ka[3]=a0.w;
    ka[4]=a1.x; ka[5]=a1.y; ka[6]=a1.z; ka[7]=a1.w;
    kb[0]=b0.x; kb[1]=b0.y; kb[2]=b0.z; kb[3]=b0.w;
    kb[4]=b1.x; kb[5]=b1.y; kb[6]=b1.z; kb[7]=b1.w;
    int ia = 0, ib = 0;
    int base = (n >> 13) << 13;
#pragma unroll
    for (int s = 0; s < 8; s++) {
        unsigned k;
        if (ka[ia] <= kb[ib]) k = ka[ia++]; else k = kb[ib++];
        g_nbr[(size_t)n * 8 + s] = base + (int)(k & 0x1FFFu);
    }
}

// ---------------- GEMM1 + fused BN1 partial stats ----------------------------
__global__ void k_gemm1(const float* __restrict__ feats, const float* __restrict__ w1) {
    __shared__ float c_s[32 * COMB];
    int base = blockIdx.x * 32;
    int ch = threadIdx.x;
    for (int idx = threadIdx.x; idx < 32 * 9; idx += 128) {
        int p = idx / 9, slot = idx - p * 9;
        int src = (slot == 0) ? (base + p) : g_nbr[(base + p) * 8 + slot - 1];
        const float4* s4 = (const float4*)(feats + (size_t)src * 8);
        float4* dst = (float4*)&c_s[p * COMB + slot * 8];
        dst[0] = s4[0]; dst[1] = s4[1];
    }
    float wreg[COMB];
#pragma unroll
    for (int k = 0; k < COMB; k++) wreg[k] = w1[k * HDIM + ch];
    __syncthreads();

    float s = 0.f, q = 0.f;
    for (int p = 0; p < 32; p++) {
        const float4* cp = (const float4*)(c_s + p * COMB);
        float acc = 0.f;
#pragma unroll
        for (int k4 = 0; k4 < COMB / 4; k4++) {
            float4 cv = cp[k4];
            acc += cv.x * wreg[k4 * 4]     + cv.y * wreg[k4 * 4 + 1]
                 + cv.z * wreg[k4 * 4 + 2] + cv.w * wreg[k4 * 4 + 3];
        }
        g_pre1[(size_t)(base + p) * HDIM + ch] = acc;
        s += acc; q += acc * acc;
    }
    g_part[blockIdx.x * HDIM + ch] = s;
    g_part[SQOFF + blockIdx.x * HDIM + ch] = q;
}

// ---------------- BN partials for pre2 ---------------------------------------
__global__ void k_bnstats2() {
    int ch = threadIdx.x;
    float s = 0.f, q = 0.f;
    const float* p = g_pre2 + (size_t)blockIdx.x * 128 * HDIM + ch;
#pragma unroll 4
    for (int r = 0; r < 128; r++) {
        float v = p[r * HDIM];
        s += v; q += v * v;
    }
    g_part[blockIdx.x * HDIM + ch] = s;
    g_part[SQOFF + blockIdx.x * HDIM + ch] = q;
}

__global__ void k_bnfin(const float* __restrict__ gamma, const float* __restrict__ beta,
                        int which, int npart) {
    int ch = threadIdx.x;
    float s = 0.f, q = 0.f;
#pragma unroll 8
    for (int i = 0; i < npart; i++) {
        s += g_part[i * HDIM + ch];
        q += g_part[SQOFF + i * HDIM + ch];
    }
    float mu  = s * (1.f / NPTS);
    float var = q * (1.f / NPTS) - mu * mu;
    float sc  = rsqrtf(var + 1e-5f) * gamma[ch];
    float* st = which ? g_stats2 : g_stats1;
    st[ch]        = sc;
    st[HDIM + ch] = beta[ch] - mu * sc;
}

// ---------------- apply BN1 + ReLU -> h (tf32-rounded) -----------------------
__global__ void k_happly() {
    int i = blockIdx.x * 256 + threadIdx.x;
    float4 v = ((const float4*)g_pre1)[i];
    int c = (i & 31) << 2;
    float4 u;
    u.x = fmaxf(v.x * g_stats1[c]     + g_stats1[HDIM + c],     0.f);
    u.y = fmaxf(v.y * g_stats1[c + 1] + g_stats1[HDIM + c + 1], 0.f);
    u.z = fmaxf(v.z * g_stats1[c + 2] + g_stats1[HDIM + c + 2], 0.f);
    u.w = fmaxf(v.w * g_stats1[c + 3] + g_stats1[HDIM + c + 3], 0.f);
    u.x = __uint_as_float(f2tf(u.x));
    u.y = __uint_as_float(f2tf(u.y));
    u.z = __uint_as_float(f2tf(u.z));
    u.w = __uint_as_float(f2tf(u.w));
    ((float4*)g_h)[i] = u;
}

// ---------------- pre-round w3 to tf32 ---------------------------------------
__global__ void k_wprep(const float* __restrict__ w3) {
    int i = blockIdx.x * 256 + threadIdx.x;   // float4 units: 110592
    float4 v = ((const float4*)w3)[i];
    float4 u;
    u.x = __uint_as_float(f2tf(v.x));
    u.y = __uint_as_float(f2tf(v.y));
    u.z = __uint_as_float(f2tf(v.z));
    u.w = __uint_as_float(f2tf(v.w));
    ((float4*)g_w3t)[i] = u;
}

// ---------------- sparse conv: pipelined tf32 MMA GEMM -----------------------
// K_total = 27*128 = 3456, chunk=32, 108 chunks, 3-stage cp.async pipeline.
#define APAD 36    // ≡4 mod 32
#define WPAD 136   // ≡8 mod 32
#define A_FLOATS (128 * APAD)           // 4608
#define W_FLOATS (32 * WPAD)            // 4352
#define CONV_SMEM ((3 * (A_FLOATS + W_FLOATS)) * 4 + 27 * 128 * 4)

__global__ void __launch_bounds__(256, 1)
k_conv(const int* __restrict__ coords) {
    extern __shared__ float sm[];
    float* A_base = sm;                               // 3 stages
    float* W_base = sm + 3 * A_FLOATS;
    int*   j_s    = (int*)(sm + 3 * (A_FLOATS + W_FLOATS));
    int base = blockIdx.x * 128;
    int tid  = threadIdx.x;

    for (int idx = tid; idx < 27 * 128; idx += 256) {
        int o = idx >> 7, p = idx & 127;
        int4 c = ((const int4*)coords)[base + p];
        int ox = o / 9 - 1, oy = (o / 3) % 3 - 1, oz = o % 3 - 1;
        int key = ((c.x * 64 + c.y + 1 + ox) * 64 + (c.z + 1 + oy)) * 64 + (c.w + 1 + oz);
        j_s[idx] = g_table[key];
    }
    __syncthreads();

    auto load_chunk = [&](int c, int buf) {
        int o = c >> 2, kin = (c & 3) * 32;
        float* As = A_base + buf * A_FLOATS;
        float* Ws = W_base + buf * W_FLOATS;
#pragma unroll
        for (int qq = 0; qq < 4; qq++) {
            int idx = tid + qq * 256;               // 0..1023
            int p = idx >> 3, part = idx & 7;
            int j = j_s[(o << 7) + p];
            int sz = (j >= 0) ? 16 : 0;
            int jc = j >= 0 ? j : 0;
            cp16(&As[p * APAD + part * 4],
                 g_h + (size_t)jc * HDIM + kin + part * 4, sz);
        }
        const float* wsrc = g_w3t + ((size_t)o * 128 + kin) * HDIM;
#pragma unroll
        for (int qq = 0; qq < 4; qq++) {
            int idx = tid + qq * 256;
            int k = idx >> 5, part = idx & 31;
            cp16(&Ws[k * WPAD + part * 4], wsrc + k * HDIM + part * 4, 16);
        }
        cp_commit();
    };

    int lane = tid & 31, warp = tid >> 5;
    int gid = lane >> 2, tig = lane & 3;
    int mgrp = warp >> 1;
    int ngrp = warp & 1;

    float acc[2][8][4];
#pragma unroll
    for (int mt = 0; mt < 2; mt++)
#pragma unroll
        for (int nt = 0; nt < 8; nt++)
#pragma unroll
            for (int r = 0; r < 4; r++) acc[mt][nt][r] = 0.f;

    load_chunk(0, 0);
    load_chunk(1, 1);

    for (int c = 0; c < 108; c++) {
        cp_wait<1>();
        __syncthreads();
        if (c + 2 < 108) load_chunk(c + 2, (c + 2) % 3);
        const float* As = A_base + (c % 3) * A_FLOATS;
        const float* Ws = W_base + (c % 3) * W_FLOATS;
#pragma unroll
        for (int kt = 0; kt < 4; kt++) {
            int k0 = kt * 8;
            unsigned a[2][4];
#pragma unroll
            for (int mt = 0; mt < 2; mt++) {
                int pr = mgrp * 32 + mt * 16;
                a[mt][0] = __float_as_uint(As[(pr + gid) * APAD + k0 + tig]);
                a[mt][1] = __float_as_uint(As[(pr + gid + 8) * APAD + k0 + tig]);
                a[mt][2] = __float_as_uint(As[(pr + gid) * APAD + k0 + tig + 4]);
                a[mt][3] = __float_as_uint(As[(pr + gid + 8) * APAD + k0 + tig + 4]);
            }
#pragma unroll
            for (int nt = 0; nt < 8; nt++) {
                int nc = ngrp * 64 + nt * 8;
                unsigned b0 = __float_as_uint(Ws[(k0 + tig) * WPAD + nc + gid]);
                unsigned b1 = __float_as_uint(Ws[(k0 + tig + 4) * WPAD + nc + gid]);
                mma_tf32(acc[0][nt], a[0], b0, b1);
                mma_tf32(acc[1][nt], a[1], b0, b1);
            }
        }
        __syncthreads();
    }

#pragma unroll
    for (int mt = 0; mt < 2; mt++) {
#pragma unroll
        for (int nt = 0; nt < 8; nt++) {
            int row0 = base + mgrp * 32 + mt * 16 + gid;
            int col  = ngrp * 64 + nt * 8 + tig * 2;
            *(float2*)&g_pre2[(size_t)row0 * HDIM + col] =
                make_float2(acc[mt][nt][0], acc[mt][nt][1]);
            *(float2*)&g_pre2[(size_t)(row0 + 8) * HDIM + col] =
                make_float2(acc[mt][nt][2], acc[mt][nt][3]);
        }
    }
}

// ---------------- final -------------------------------------------------------
__global__ void k_final(const float* __restrict__ w_out, float* __restrict__ out) {
    __shared__ float h_s[16 * HDIM];
    __shared__ float w_s[HDIM * 16];
    int base = blockIdx.x * 16;
    for (int i = threadIdx.x; i < HDIM * 16; i += 256) w_s[i] = w_out[i];
    for (int i = threadIdx.x; i < 16 * HDIM; i += 256) {
        int ch = i & 127;
        float v = g_pre2[(size_t)base * HDIM + i];
        v = v * g_stats2[ch] + g_stats2[HDIM + ch];
        h_s[i] = fmaxf(v, 0.f);
    }
    __syncthreads();
    int p = threadIdx.x >> 4, oc = threadIdx.x & 15;
    float acc = 0.f;
#pragma unroll 8
    for (int k = 0; k < HDIM; k++)
        acc += h_s[p * HDIM + k] * w_s[k * 16 + oc];
    out[(size_t)(base + p) * 16 + oc] = acc;
}

// ---------------- launcher ----------------------------------------------------
extern "C" void kernel_launch(void* const* d_in, const int* in_sizes, int n_in,
                              void* d_out, int out_size) {
    const int*   coords = (const int*)  d_in[0];
    const float* feats  = (const float*)d_in[1];
    const float* w1     = (const float*)d_in[2];
    const float* g1     = (const float*)d_in[3];
    const float* b1     = (const float*)d_in[4];
    const float* w3     = (const float*)d_in[5];
    const float* g2     = (const float*)d_in[6];
    const float* b2     = (const float*)d_in[7];
    const float* w_out  = (const float*)d_in[8];
    float* out = (float*)d_out;

    cudaFuncSetAttribute(k_conv, cudaFuncAttributeMaxDynamicSharedMemorySize, CONV_SMEM);

    k_init    <<<TABSZ / 256, 256>>>();
    k_build   <<<NPTS / 256, 256>>>(coords);
    k_wprep   <<<27 * HDIM * HDIM / 1024, 256>>>(w3);
    k_knn2    <<<256, 256>>>(coords);
    k_kmerge  <<<NPTS / 256, 256>>>();
    k_gemm1   <<<NPTS / 32, 128>>>(feats, w1);
    k_bnfin   <<<1, 128>>>(g1, b1, 0, 1024);
    k_happly  <<<NPTS * 32 / 256, 256>>>();
    k_conv    <<<NPTS / 128, 256, CONV_SMEM>>>(coords);
    k_bnstats2<<<256, 128>>>();
    k_bnfin   <<<1, 128>>>(g2, b2, 1, 256);
    k_final   <<<NPTS / 16, 256>>>(w_out, out);
}

// round 10
// speedup vs baseline: 3.0156x; 1.0038x over previous
#include <cuda_runtime.h>
#include <cstdint>

#define NPTS   32768
#define NBATCH 4
#define MPER   8192
#define KNN    8
#define HDIM   128
#define COMB   72
#define TABSZ  (4*64*64*64)
#define KSLICE 8
#define CAND   (MPER / KSLICE)   // 1024 candidates per knn block

// ---------------- scratch ----------------------------------------------------
__device__ int      g_table[TABSZ];
__device__ unsigned g_kk[KSLICE * NPTS * KNN];   // per-slice sorted top-8 keys
__device__ int      g_nbr[NPTS * KNN];
__device__ float    g_pre1[NPTS * HDIM];
__device__ float    g_h[NPTS * HDIM];            // tf32-rounded bits
__device__ float    g_w3t[27 * HDIM * HDIM];     // tf32-rounded w3
__device__ float    g_pre2[NPTS * HDIM];
#define SQOFF (1024 * HDIM)
__device__ float    g_part[2 * 1024 * HDIM];
__device__ float    g_stats1[2 * HDIM];
__device__ float    g_stats2[2 * HDIM];

// ---------------- helpers ----------------------------------------------------
__device__ __forceinline__ unsigned f2tf(float f) {
    unsigned u;
    asm("cvt.rna.tf32.f32 %0, %1;" : "=r"(u) : "f"(f));
    return u;
}
__device__ __forceinline__ void mma_tf32(float* c, const unsigned* a,
                                         unsigned b0, unsigned b1) {
    asm volatile(
        "mma.sync.aligned.m16n8k8.row.col.f32.tf32.tf32.f32 "
        "{%0,%1,%2,%3},{%4,%5,%6,%7},{%8,%9},{%0,%1,%2,%3};"
        : "+f"(c[0]), "+f"(c[1]), "+f"(c[2]), "+f"(c[3])
        : "r"(a[0]), "r"(a[1]), "r"(a[2]), "r"(a[3]), "r"(b0), "r"(b1));
}
__device__ __forceinline__ void cp16(void* dst, const void* src, int bytes) {
    unsigned d = (unsigned)__cvta_generic_to_shared(dst);
    asm volatile("cp.async.ca.shared.global [%0], [%1], 16, %2;"
                 :: "r"(d), "l"(src), "r"(bytes));
}
__device__ __forceinline__ void cp_commit() {
    asm volatile("cp.async.commit_group;");
}
template <int N> __device__ __forceinline__ void cp_wait() {
    asm volatile("cp.async.wait_group %0;" :: "n"(N));
}

// ---------------- table -------------------------------------------------------
__global__ void k_init() { g_table[blockIdx.x * 256 + threadIdx.x] = -1; }

__global__ void k_build(const int* __restrict__ coords) {
    int n = blockIdx.x * 256 + threadIdx.x;
    int4 c = ((const int4*)coords)[n];
    g_table[((c.x * 64 + c.y + 1) * 64 + (c.z + 1)) * 64 + (c.w + 1)] = n;
}

// ---------------- kNN: 8-way candidate split ---------------------------------
// grid 1024 = batch(4) x slice(8) x query-block(32); 256 threads = 256 queries.
__global__ void k_knn2(const int* __restrict__ coords) {
    __shared__ int pc[CAND];   // 4 KB
    int blk   = blockIdx.x;
    int b     = blk >> 8;
    int slice = (blk >> 5) & 7;
    int qb    = blk & 31;
    int base  = b * MPER;
    int cbase = base + slice * CAND;

    for (int i = threadIdx.x; i < CAND; i += 256) {
        const int* c = coords + (size_t)(cbase + i) * 4;
        pc[i] = c[1] | (c[2] << 8) | (c[3] << 16);
    }
    int n = base + qb * 256 + threadIdx.x;
    const int* qc = coords + (size_t)n * 4;
    unsigned q = (unsigned)(qc[1] | (qc[2] << 8) | (qc[3] << 16));
    __syncthreads();

    unsigned best[8];
#pragma unroll
    for (int s = 0; s < 8; s++) best[s] = 0xFFFFFFFFu;

    auto eval = [&](unsigned pcv, unsigned idx) {
        unsigned ad = __vabsdiffu4(q, pcv);
        unsigned d2 = __dp4a(ad, ad, 0u);
        unsigned key = d2 * 8192u + idx;          // exact (d2<<13)|idx, 1 IMAD
        if (key < best[7]) {
#pragma unroll
            for (int s = 0; s < 8; s++) {
                unsigned mx = key > best[s] ? key : best[s];
                best[s]     = key < best[s] ? key : best[s];
                key = mx;
            }
        }
    };

    unsigned ioff = (unsigned)(slice * CAND);
    const int4* pc4 = (const int4*)pc;
#pragma unroll 2
    for (int i4 = 0; i4 < CAND / 4; i4++) {
        int4 v = pc4[i4];
        unsigned i = ioff + (unsigned)(i4 * 4);
        eval((unsigned)v.x, i);
        eval((unsigned)v.y, i + 1);
        eval((unsigned)v.z, i + 2);
        eval((unsigned)v.w, i + 3);
    }
#pragma unroll
    for (int s = 0; s < 8; s++)
        g_kk[(size_t)slice * NPTS * 8 + (size_t)n * 8 + s] = best[s];
}

// ---------------- merge 8 sorted 8-lists -> global top-8 ---------------------
__global__ void k_kmerge() {
    int n = blockIdx.x * 256 + threadIdx.x;
    unsigned best[8];
#pragma unroll
    for (int s = 0; s < 8; s++) best[s] = 0xFFFFFFFFu;

    auto feed = [&](unsigned key) {
        if (key < best[7]) {
#pragma unroll
            for (int s = 0; s < 8; s++) {
                unsigned mx = key > best[s] ? key : best[s];
                best[s]     = key < best[s] ? key : best[s];
                key = mx;
            }
        }
    };

#pragma unroll
    for (int l = 0; l < KSLICE; l++) {
        const uint4* p = (const uint4*)&g_kk[(size_t)l * NPTS * 8 + (size_t)n * 8];
        uint4 a = p[0], bq = p[1];
        feed(a.x);  feed(a.y);  feed(a.z);  feed(a.w);
        feed(bq.x); feed(bq.y); feed(bq.z); feed(bq.w);
    }
    int base = (n >> 13) << 13;
#pragma unroll
    for (int s = 0; s < 8; s++)
        g_nbr[(size_t)n * 8 + s] = base + (int)(best[s] & 0x1FFFu);
}

// ---------------- GEMM1 + fused BN1 partial stats ----------------------------
__global__ void k_gemm1(const float* __restrict__ feats, const float* __restrict__ w1) {
    __shared__ float c_s[32 * COMB];
    int base = blockIdx.x * 32;
    int ch = threadIdx.x;
    for (int idx = threadIdx.x; idx < 32 * 9; idx += 128) {
        int p = idx / 9, slot = idx - p * 9;
        int src = (slot == 0) ? (base + p) : g_nbr[(base + p) * 8 + slot - 1];
        const float4* s4 = (const float4*)(feats + (size_t)src * 8);
        float4* dst = (float4*)&c_s[p * COMB + slot * 8];
        dst[0] = s4[0]; dst[1] = s4[1];
    }
    float wreg[COMB];
#pragma unroll
    for (int k = 0; k < COMB; k++) wreg[k] = w1[k * HDIM + ch];
    __syncthreads();

    float s = 0.f, q = 0.f;
    for (int p = 0; p < 32; p++) {
        const float4* cp = (const float4*)(c_s + p * COMB);
        float acc = 0.f;
#pragma unroll
        for (int k4 = 0; k4 < COMB / 4; k4++) {
            float4 cv = cp[k4];
            acc += cv.x * wreg[k4 * 4]     + cv.y * wreg[k4 * 4 + 1]
                 + cv.z * wreg[k4 * 4 + 2] + cv.w * wreg[k4 * 4 + 3];
        }
        g_pre1[(size_t)(base + p) * HDIM + ch] = acc;
        s += acc; q += acc * acc;
    }
    g_part[blockIdx.x * HDIM + ch] = s;
    g_part[SQOFF + blockIdx.x * HDIM + ch] = q;
}

// ---------------- BN partials for pre2 ---------------------------------------
__global__ void k_bnstats2() {
    int ch = threadIdx.x;
    float s = 0.f, q = 0.f;
    const float* p = g_pre2 + (size_t)blockIdx.x * 128 * HDIM + ch;
#pragma unroll 4
    for (int r = 0; r < 128; r++) {
        float v = p[r * HDIM];
        s += v; q += v * v;
    }
    g_part[blockIdx.x * HDIM + ch] = s;
    g_part[SQOFF + blockIdx.x * HDIM + ch] = q;
}

__global__ void k_bnfin(const float* __restrict__ gamma, const float* __restrict__ beta,
                        int which, int npart) {
    int ch = threadIdx.x;
    float s = 0.f, q = 0.f;
#pragma unroll 8
    for (int i = 0; i < npart; i++) {
        s += g_part[i * HDIM + ch];
        q += g_part[SQOFF + i * HDIM + ch];
    }
    float mu  = s * (1.f / NPTS);
    float var = q * (1.f / NPTS) - mu * mu;
    float sc  = rsqrtf(var + 1e-5f) * gamma[ch];
    float* st = which ? g_stats2 : g_stats1;
    st[ch]        = sc;
    st[HDIM + ch] = beta[ch] - mu * sc;
}

// ---------------- apply BN1 + ReLU -> h (tf32-rounded) -----------------------
__global__ void k_happly() {
    int i = blockIdx.x * 256 + threadIdx.x;
    float4 v = ((const float4*)g_pre1)[i];
    int c = (i & 31) << 2;
    float4 u;
    u.x = fmaxf(v.x * g_stats1[c]     + g_stats1[HDIM + c],     0.f);
    u.y = fmaxf(v.y * g_stats1[c + 1] + g_stats1[HDIM + c + 1], 0.f);
    u.z = fmaxf(v.z * g_stats1[c + 2] + g_stats1[HDIM + c + 2], 0.f);
    u.w = fmaxf(v.w * g_stats1[c + 3] + g_stats1[HDIM + c + 3], 0.f);
    u.x = __uint_as_float(f2tf(u.x));
    u.y = __uint_as_float(f2tf(u.y));
    u.z = __uint_as_float(f2tf(u.z));
    u.w = __uint_as_float(f2tf(u.w));
    ((float4*)g_h)[i] = u;
}

// ---------------- pre-round w3 to tf32 ---------------------------------------
__global__ void k_wprep(const float* __restrict__ w3) {
    int i = blockIdx.x * 256 + threadIdx.x;   // float4 units: 110592
    float4 v = ((const float4*)w3)[i];
    float4 u;
    u.x = __uint_as_float(f2tf(v.x));
    u.y = __uint_as_float(f2tf(v.y));
    u.z = __uint_as_float(f2tf(v.z));
    u.w = __uint_as_float(f2tf(v.w));
    ((float4*)g_w3t)[i] = u;
}

// ---------------- sparse conv: pipelined tf32 MMA GEMM -----------------------
// K_total = 27*128 = 3456, chunk=32, 108 chunks, 3-stage cp.async pipeline.
#define APAD 36    // ≡4 mod 32
#define WPAD 136   // ≡8 mod 32
#define A_FLOATS (128 * APAD)           // 4608
#define W_FLOATS (32 * WPAD)            // 4352
#define CONV_SMEM ((3 * (A_FLOATS + W_FLOATS)) * 4 + 27 * 128 * 4)

__global__ void __launch_bounds__(256, 1)
k_conv(const int* __restrict__ coords) {
    extern __shared__ float sm[];
    float* A_base = sm;                               // 3 stages
    float* W_base = sm + 3 * A_FLOATS;
    int*   j_s    = (int*)(sm + 3 * (A_FLOATS + W_FLOATS));
    int base = blockIdx.x * 128;
    int tid  = threadIdx.x;

    for (int idx = tid; idx < 27 * 128; idx += 256) {
        int o = idx >> 7, p = idx & 127;
        int4 c = ((const int4*)coords)[base + p];
        int ox = o / 9 - 1, oy = (o / 3) % 3 - 1, oz = o % 3 - 1;
        int key = ((c.x * 64 + c.y + 1 + ox) * 64 + (c.z + 1 + oy)) * 64 + (c.w + 1 + oz);
        j_s[idx] = g_table[key];
    }
    __syncthreads();

    auto load_chunk = [&](int c, int buf) {
        int o = c >> 2, kin = (c & 3) * 32;
        float* As = A_base + buf * A_FLOATS;
        float* Ws = W_base + buf * W_FLOATS;
#pragma unroll
        for (int qq = 0; qq < 4; qq++) {
            int idx = tid + qq * 256;               // 0..1023
            int p = idx >> 3, part = idx & 7;
            int j = j_s[(o << 7) + p];
            int sz = (j >= 0) ? 16 : 0;
            int jc = j >= 0 ? j : 0;
            cp16(&As[p * APAD + part * 4],
                 g_h + (size_t)jc * HDIM + kin + part * 4, sz);
        }
        const float* wsrc = g_w3t + ((size_t)o * 128 + kin) * HDIM;
#pragma unroll
        for (int qq = 0; qq < 4; qq++) {
            int idx = tid + qq * 256;
            int k = idx >> 5, part = idx & 31;
            cp16(&Ws[k * WPAD + part * 4], wsrc + k * HDIM + part * 4, 16);
        }
        cp_commit();
    };

    int lane = tid & 31, warp = tid >> 5;
    int gid = lane >> 2, tig = lane & 3;
    int mgrp = warp >> 1;
    int ngrp = warp & 1;

    float acc[2][8][4];
#pragma unroll
    for (int mt = 0; mt < 2; mt++)
#pragma unroll
        for (int nt = 0; nt < 8; nt++)
#pragma unroll
            for (int r = 0; r < 4; r++) acc[mt][nt][r] = 0.f;

    load_chunk(0, 0);
    load_chunk(1, 1);

    for (int c = 0; c < 108; c++) {
        cp_wait<1>();
        __syncthreads();
        if (c + 2 < 108) load_chunk(c + 2, (c + 2) % 3);
        const float* As = A_base + (c % 3) * A_FLOATS;
        const float* Ws = W_base + (c % 3) * W_FLOATS;
#pragma unroll
        for (int kt = 0; kt < 4; kt++) {
            int k0 = kt * 8;
            unsigned a[2][4];
#pragma unroll
            for (int mt = 0; mt < 2; mt++) {
                int pr = mgrp * 32 + mt * 16;
                a[mt][0] = __float_as_uint(As[(pr + gid) * APAD + k0 + tig]);
                a[mt][1] = __float_as_uint(As[(pr + gid + 8) * APAD + k0 + tig]);
                a[mt][2] = __float_as_uint(As[(pr + gid) * APAD + k0 + tig + 4]);
                a[mt][3] = __float_as_uint(As[(pr + gid + 8) * APAD + k0 + tig + 4]);
            }
#pragma unroll
            for (int nt = 0; nt < 8; nt++) {
                int nc = ngrp * 64 + nt * 8;
                unsigned b0 = __float_as_uint(Ws[(k0 + tig) * WPAD + nc + gid]);
                unsigned b1 = __float_as_uint(Ws[(k0 + tig + 4) * WPAD + nc + gid]);
                mma_tf32(acc[0][nt], a[0], b0, b1);
                mma_tf32(acc[1][nt], a[1], b0, b1);
            }
        }
        __syncthreads();
    }

#pragma unroll
    for (int mt = 0; mt < 2; mt++) {
#pragma unroll
        for (int nt = 0; nt < 8; nt++) {
            int row0 = base + mgrp * 32 + mt * 16 + gid;
            int col  = ngrp * 64 + nt * 8 + tig * 2;
            *(float2*)&g_pre2[(size_t)row0 * HDIM + col] =
                make_float2(acc[mt][nt][0], acc[mt][nt][1]);
            *(float2*)&g_pre2[(size_t)(row0 + 8) * HDIM + col] =
                make_float2(acc[mt][nt][2], acc[mt][nt][3]);
        }
    }
}

// ---------------- final -------------------------------------------------------
__global__ void k_final(const float* __restrict__ w_out, float* __restrict__ out) {
    __shared__ float h_s[16 * HDIM];
    __shared__ float w_s[HDIM * 16];
    int base = blockIdx.x * 16;
    for (int i = threadIdx.x; i < HDIM * 16; i += 256) w_s[i] = w_out[i];
    for (int i = threadIdx.x; i < 16 * HDIM; i += 256) {
        int ch = i & 127;
        float v = g_pre2[(size_t)base * HDIM + i];
        v = v * g_stats2[ch] + g_stats2[HDIM + ch];
        h_s[i] = fmaxf(v, 0.f);
    }
    __syncthreads();
    int p = threadIdx.x >> 4, oc = threadIdx.x & 15;
    float acc = 0.f;
#pragma unroll 8
    for (int k = 0; k < HDIM; k++)
        acc += h_s[p * HDIM + k] * w_s[k * 16 + oc];
    out[(size_t)(base + p) * 16 + oc] = acc;
}

// ---------------- launcher ----------------------------------------------------
extern "C" void kernel_launch(void* const* d_in, const int* in_sizes, int n_in,
                              void* d_out, int out_size) {
    const int*   coords = (const int*)  d_in[0];
    const float* feats  = (const float*)d_in[1];
    const float* w1     = (const float*)d_in[2];
    const float* g1     = (const float*)d_in[3];
    const float* b1     = (const float*)d_in[4];
    const float* w3     = (const float*)d_in[5];
    const float* g2     = (const float*)d_in[6];
    const float* b2     = (const float*)d_in[7];
    const float* w_out  = (const float*)d_in[8];
    float* out = (float*)d_out;

    cudaFuncSetAttribute(k_conv, cudaFuncAttributeMaxDynamicSharedMemorySize, CONV_SMEM);

    k_init    <<<TABSZ / 256, 256>>>();
    k_build   <<<NPTS / 256, 256>>>(coords);
    k_wprep   <<<27 * HDIM * HDIM / 1024, 256>>>(w3);
    k_knn2    <<<NBATCH * KSLICE * 32, 256>>>(coords);
    k_kmerge  <<<NPTS / 256, 256>>>();
    k_gemm1   <<<NPTS / 32, 128>>>(feats, w1);
    k_bnfin   <<<1, 128>>>(g1, b1, 0, 1024);
    k_happly  <<<NPTS * 32 / 256, 256>>>();
    k_conv    <<<NPTS / 128, 256, CONV_SMEM>>>(coords);
    k_bnstats2<<<256, 128>>>();
    k_bnfin   <<<1, 128>>>(g2, b2, 1, 256);
    k_final   <<<NPTS / 16, 256>>>(w_out, out);
}

// round 11
// speedup vs baseline: 4.0393x; 1.3395x over previous
#include <cuda_runtime.h>
#include <cstdint>

#define NPTS   32768
#define NBATCH 4
#define MPER   8192
#define KNN    8
#define HDIM   128
#define COMB   72
#define TABSZ  (4*64*64*64)

// ---------------- scratch ----------------------------------------------------
__device__ int      g_table[TABSZ];
__device__ int2     g_soff[343];          // (key-offset, d2) sorted by d2
__device__ int      g_nbr[NPTS * KNN];
__device__ float    g_pre1[NPTS * HDIM];
__device__ float    g_h[NPTS * HDIM];            // tf32-rounded bits
__device__ float    g_w3t[27 * HDIM * HDIM];     // tf32-rounded w3
__device__ float    g_pre2[NPTS * HDIM];
#define SQOFF (1024 * HDIM)
__device__ float    g_part[2 * 1024 * HDIM];
__device__ float    g_stats1[2 * HDIM];
__device__ float    g_stats2[2 * HDIM];

// ---------------- helpers ----------------------------------------------------
__device__ __forceinline__ unsigned f2tf(float f) {
    unsigned u;
    asm("cvt.rna.tf32.f32 %0, %1;" : "=r"(u) : "f"(f));
    return u;
}
__device__ __forceinline__ void mma_tf32(float* c, const unsigned* a,
                                         unsigned b0, unsigned b1) {
    asm volatile(
        "mma.sync.aligned.m16n8k8.row.col.f32.tf32.tf32.f32 "
        "{%0,%1,%2,%3},{%4,%5,%6,%7},{%8,%9},{%0,%1,%2,%3};"
        : "+f"(c[0]), "+f"(c[1]), "+f"(c[2]), "+f"(c[3])
        : "r"(a[0]), "r"(a[1]), "r"(a[2]), "r"(a[3]), "r"(b0), "r"(b1));
}
__device__ __forceinline__ void cp16(void* dst, const void* src, int bytes) {
    unsigned d = (unsigned)__cvta_generic_to_shared(dst);
    asm volatile("cp.async.ca.shared.global [%0], [%1], 16, %2;"
                 :: "r"(d), "l"(src), "r"(bytes));
}
__device__ __forceinline__ void cp_commit() {
    asm volatile("cp.async.commit_group;");
}
template <int N> __device__ __forceinline__ void cp_wait() {
    asm volatile("cp.async.wait_group %0;" :: "n"(N));
}

// ---------------- table -------------------------------------------------------
__global__ void k_init() { g_table[blockIdx.x * 256 + threadIdx.x] = -1; }

__global__ void k_build(const int* __restrict__ coords) {
    int n = blockIdx.x * 256 + threadIdx.x;
    int4 c = ((const int4*)coords)[n];
    g_table[((c.x * 64 + c.y + 1) * 64 + (c.z + 1)) * 64 + (c.w + 1)] = n;
}

// ---------------- sorted offset list (7^3 cube, ascending d2) ----------------
__global__ void k_offinit() {
    __shared__ int d2s[343];
    int t = threadIdx.x;
    if (t < 343) {
        int ox = t / 49 - 3, oy = (t / 7) % 7 - 3, oz = t % 7 - 3;
        d2s[t] = ox * ox + oy * oy + oz * oz;
    }
    __syncthreads();
    if (t < 343) {
        int ox = t / 49 - 3, oy = (t / 7) % 7 - 3, oz = t % 7 - 3;
        int d2 = d2s[t];
        int rank = 0;
        for (int j = 0; j < 343; j++) {
            int dj = d2s[j];
            rank += (dj < d2) || (dj == d2 && j < t);
        }
        g_soff[rank] = make_int2(ox * 4096 + oy * 64 + oz, d2);
    }
}

// ---------------- grid-shell exact kNN ---------------------------------------
// Probes voxels in ascending-d2 order; identical keys (d2*8192+idx) => identical
// result to brute force. Aliased probes hit never-written slots (-1); only
// key<0 needs a guard. Fallback shells R=4..31 for sparse corners.
__global__ void k_knng(const int* __restrict__ coords) {
    __shared__ int2 soff[343];
    for (int i = threadIdx.x; i < 343; i += 256) soff[i] = g_soff[i];
    __syncthreads();

    int n = blockIdx.x * 256 + threadIdx.x;
    int4 c = ((const int4*)coords)[n];
    int qkey = ((c.x * 64 + c.y + 1) * 64 + (c.z + 1)) * 64 + (c.w + 1);

    unsigned best[8];
#pragma unroll
    for (int s = 0; s < 8; s++) best[s] = 0xFFFFFFFFu;

    auto insert = [&](unsigned key) {
        if (key < best[7]) {
#pragma unroll
            for (int s = 0; s < 8; s++) {
                unsigned mx = key > best[s] ? key : best[s];
                best[s]     = key < best[s] ? key : best[s];
                key = mx;
            }
        }
    };

    // main sorted scan with 1-deep load prefetch
    int2 od = soff[0];
    int key0 = qkey + od.x;
    int jcur = (key0 >= 0) ? g_table[key0] : -1;
    for (int it = 0; it < 343; it++) {
        int2 odn = soff[(it + 1 < 343) ? it + 1 : it];
        int keyn = qkey + odn.x;
        int jn = (keyn >= 0) ? g_table[keyn] : -1;   // prefetch next
        if ((unsigned)od.y > (best[7] >> 13)) break; // sorted => nothing later wins
        if (jcur >= 0)
            insert((unsigned)od.y * 8192u + (unsigned)(jcur & 8191));
        od = odn; jcur = jn;
    }

    // fallback shells (rare: sparse corners/edges). After shell R-1, unseen
    // points have d2 >= R^2; stop when best8th d2 < R^2. R=31 covers grid.
    for (int R = 4; R <= 31; R++) {
        if ((best[7] >> 13) < (unsigned)(R * R)) break;
        for (int ox = -R; ox <= R; ox++) {
            for (int oy = -R; oy <= R; oy++) {
                bool face = (ox == -R || ox == R || oy == -R || oy == R);
                int zstep = face ? 1 : 2 * R;
                for (int oz = -R; oz <= R; oz += zstep) {
                    int key = qkey + ox * 4096 + oy * 64 + oz;
                    if (key < 0) continue;
                    int j = g_table[key];
                    if (j >= 0) {
                        int d2 = ox * ox + oy * oy + oz * oz;
                        insert((unsigned)d2 * 8192u + (unsigned)(j & 8191));
                    }
                }
            }
        }
    }

    int base = (n >> 13) << 13;
#pragma unroll
    for (int s = 0; s < 8; s++)
        g_nbr[(size_t)n * 8 + s] = base + (int)(best[s] & 0x1FFFu);
}

// ---------------- GEMM1 + fused BN1 partial stats ----------------------------
__global__ void k_gemm1(const float* __restrict__ feats, const float* __restrict__ w1) {
    __shared__ float c_s[32 * COMB];
    int base = blockIdx.x * 32;
    int ch = threadIdx.x;
    for (int idx = threadIdx.x; idx < 32 * 9; idx += 128) {
        int p = idx / 9, slot = idx - p * 9;
        int src = (slot == 0) ? (base + p) : g_nbr[(base + p) * 8 + slot - 1];
        const float4* s4 = (const float4*)(feats + (size_t)src * 8);
        float4* dst = (float4*)&c_s[p * COMB + slot * 8];
        dst[0] = s4[0]; dst[1] = s4[1];
    }
    float wreg[COMB];
#pragma unroll
    for (int k = 0; k < COMB; k++) wreg[k] = w1[k * HDIM + ch];
    __syncthreads();

    float s = 0.f, q = 0.f;
    for (int p = 0; p < 32; p++) {
        const float4* cp = (const float4*)(c_s + p * COMB);
        float acc = 0.f;
#pragma unroll
        for (int k4 = 0; k4 < COMB / 4; k4++) {
            float4 cv = cp[k4];
            acc += cv.x * wreg[k4 * 4]     + cv.y * wreg[k4 * 4 + 1]
                 + cv.z * wreg[k4 * 4 + 2] + cv.w * wreg[k4 * 4 + 3];
        }
        g_pre1[(size_t)(base + p) * HDIM + ch] = acc;
        s += acc; q += acc * acc;
    }
    g_part[blockIdx.x * HDIM + ch] = s;
    g_part[SQOFF + blockIdx.x * HDIM + ch] = q;
}

// ---------------- BN partials for pre2 ---------------------------------------
__global__ void k_bnstats2() {
    int ch = threadIdx.x;
    float s = 0.f, q = 0.f;
    const float* p = g_pre2 + (size_t)blockIdx.x * 128 * HDIM + ch;
#pragma unroll 4
    for (int r = 0; r < 128; r++) {
        float v = p[r * HDIM];
        s += v; q += v * v;
    }
    g_part[blockIdx.x * HDIM + ch] = s;
    g_part[SQOFF + blockIdx.x * HDIM + ch] = q;
}

__global__ void k_bnfin(const float* __restrict__ gamma, const float* __restrict__ beta,
                        int which, int npart) {
    int ch = threadIdx.x;
    float s = 0.f, q = 0.f;
#pragma unroll 8
    for (int i = 0; i < npart; i++) {
        s += g_part[i * HDIM + ch];
        q += g_part[SQOFF + i * HDIM + ch];
    }
    float mu  = s * (1.f / NPTS);
    float var = q * (1.f / NPTS) - mu * mu;
    float sc  = rsqrtf(var + 1e-5f) * gamma[ch];
    float* st = which ? g_stats2 : g_stats1;
    st[ch]        = sc;
    st[HDIM + ch] = beta[ch] - mu * sc;
}

// ---------------- apply BN1 + ReLU -> h (tf32-rounded) -----------------------
__global__ void k_happly() {
    int i = blockIdx.x * 256 + threadIdx.x;
    float4 v = ((const float4*)g_pre1)[i];
    int c = (i & 31) << 2;
    float4 u;
    u.x = fmaxf(v.x * g_stats1[c]     + g_stats1[HDIM + c],     0.f);
    u.y = fmaxf(v.y * g_stats1[c + 1] + g_stats1[HDIM + c + 1], 0.f);
    u.z = fmaxf(v.z * g_stats1[c + 2] + g_stats1[HDIM + c + 2], 0.f);
    u.w = fmaxf(v.w * g_stats1[c + 3] + g_stats1[HDIM + c + 3], 0.f);
    u.x = __uint_as_float(f2tf(u.x));
    u.y = __uint_as_float(f2tf(u.y));
    u.z = __uint_as_float(f2tf(u.z));
    u.w = __uint_as_float(f2tf(u.w));
    ((float4*)g_h)[i] = u;
}

// ---------------- pre-round w3 to tf32 ---------------------------------------
__global__ void k_wprep(const float* __restrict__ w3) {
    int i = blockIdx.x * 256 + threadIdx.x;   // float4 units: 110592
    float4 v = ((const float4*)w3)[i];
    float4 u;
    u.x = __uint_as_float(f2tf(v.x));
    u.y = __uint_as_float(f2tf(v.y));
    u.z = __uint_as_float(f2tf(v.z));
    u.w = __uint_as_float(f2tf(v.w));
    ((float4*)g_w3t)[i] = u;
}

// ---------------- sparse conv: pipelined tf32 MMA GEMM -----------------------
// K_total = 27*128 = 3456, chunk=32, 108 chunks, 3-stage cp.async pipeline.
#define APAD 36    // ≡4 mod 32
#define WPAD 136   // ≡8 mod 32
#define A_FLOATS (128 * APAD)           // 4608
#define W_FLOATS (32 * WPAD)            // 4352
#define CONV_SMEM ((3 * (A_FLOATS + W_FLOATS)) * 4 + 27 * 128 * 4)

__global__ void __launch_bounds__(256, 1)
k_conv(const int* __restrict__ coords) {
    extern __shared__ float sm[];
    float* A_base = sm;                               // 3 stages
    float* W_base = sm + 3 * A_FLOATS;
    int*   j_s    = (int*)(sm + 3 * (A_FLOATS + W_FLOATS));
    int base = blockIdx.x * 128;
    int tid  = threadIdx.x;

    for (int idx = tid; idx < 27 * 128; idx += 256) {
        int o = idx >> 7, p = idx & 127;
        int4 c = ((const int4*)coords)[base + p];
        int ox = o / 9 - 1, oy = (o / 3) % 3 - 1, oz = o % 3 - 1;
        int key = ((c.x * 64 + c.y + 1 + ox) * 64 + (c.z + 1 + oy)) * 64 + (c.w + 1 + oz);
        j_s[idx] = g_table[key];
    }
    __syncthreads();

    auto load_chunk = [&](int c, int buf) {
        int o = c >> 2, kin = (c & 3) * 32;
        float* As = A_base + buf * A_FLOATS;
        float* Ws = W_base + buf * W_FLOATS;
#pragma unroll
        for (int qq = 0; qq < 4; qq++) {
            int idx = tid + qq * 256;               // 0..1023
            int p = idx >> 3, part = idx & 7;
            int j = j_s[(o << 7) + p];
            int sz = (j >= 0) ? 16 : 0;
            int jc = j >= 0 ? j : 0;
            cp16(&As[p * APAD + part * 4],
                 g_h + (size_t)jc * HDIM + kin + part * 4, sz);
        }
        const float* wsrc = g_w3t + ((size_t)o * 128 + kin) * HDIM;
#pragma unroll
        for (int qq = 0; qq < 4; qq++) {
            int idx = tid + qq * 256;
            int k = idx >> 5, part = idx & 31;
            cp16(&Ws[k * WPAD + part * 4], wsrc + k * HDIM + part * 4, 16);
        }
        cp_commit();
    };

    int lane = tid & 31, warp = tid >> 5;
    int gid = lane >> 2, tig = lane & 3;
    int mgrp = warp >> 1;
    int ngrp = warp & 1;

    float acc[2][8][4];
#pragma unroll
    for (int mt = 0; mt < 2; mt++)
#pragma unroll
        for (int nt = 0; nt < 8; nt++)
#pragma unroll
            for (int r = 0; r < 4; r++) acc[mt][nt][r] = 0.f;

    load_chunk(0, 0);
    load_chunk(1, 1);

    for (int c = 0; c < 108; c++) {
        cp_wait<1>();
        __syncthreads();
        if (c + 2 < 108) load_chunk(c + 2, (c + 2) % 3);
        const float* As = A_base + (c % 3) * A_FLOATS;
        const float* Ws = W_base + (c % 3) * W_FLOATS;
#pragma unroll
        for (int kt = 0; kt < 4; kt++) {
            int k0 = kt * 8;
            unsigned a[2][4];
#pragma unroll
            for (int mt = 0; mt < 2; mt++) {
                int pr = mgrp * 32 + mt * 16;
                a[mt][0] = __float_as_uint(As[(pr + gid) * APAD + k0 + tig]);
                a[mt][1] = __float_as_uint(As[(pr + gid + 8) * APAD + k0 + tig]);
                a[mt][2] = __float_as_uint(As[(pr + gid) * APAD + k0 + tig + 4]);
                a[mt][3] = __float_as_uint(As[(pr + gid + 8) * APAD + k0 + tig + 4]);
            }
#pragma unroll
            for (int nt = 0; nt < 8; nt++) {
                int nc = ngrp * 64 + nt * 8;
                unsigned b0 = __float_as_uint(Ws[(k0 + tig) * WPAD + nc + gid]);
                unsigned b1 = __float_as_uint(Ws[(k0 + tig + 4) * WPAD + nc + gid]);
                mma_tf32(acc[0][nt], a[0], b0, b1);
                mma_tf32(acc[1][nt], a[1], b0, b1);
            }
        }
        __syncthreads();
    }

#pragma unroll
    for (int mt = 0; mt < 2; mt++) {
#pragma unroll
        for (int nt = 0; nt < 8; nt++) {
            int row0 = base + mgrp * 32 + mt * 16 + gid;
            int col  = ngrp * 64 + nt * 8 + tig * 2;
            *(float2*)&g_pre2[(size_t)row0 * HDIM + col] =
                make_float2(acc[mt][nt][0], acc[mt][nt][1]);
            *(float2*)&g_pre2[(size_t)(row0 + 8) * HDIM + col] =
                make_float2(acc[mt][nt][2], acc[mt][nt][3]);
        }
    }
}

// ---------------- final -------------------------------------------------------
__global__ void k_final(const float* __restrict__ w_out, float* __restrict__ out) {
    __shared__ float h_s[16 * HDIM];
    __shared__ float w_s[HDIM * 16];
    int base = blockIdx.x * 16;
    for (int i = threadIdx.x; i < HDIM * 16; i += 256) w_s[i] = w_out[i];
    for (int i = threadIdx.x; i < 16 * HDIM; i += 256) {
        int ch = i & 127;
        float v = g_pre2[(size_t)base * HDIM + i];
        v = v * g_stats2[ch] + g_stats2[HDIM + ch];
        h_s[i] = fmaxf(v, 0.f);
    }
    __syncthreads();
    int p = threadIdx.x >> 4, oc = threadIdx.x & 15;
    float acc = 0.f;
#pragma unroll 8
    for (int k = 0; k < HDIM; k++)
        acc += h_s[p * HDIM + k] * w_s[k * 16 + oc];
    out[(size_t)(base + p) * 16 + oc] = acc;
}

// ---------------- launcher ----------------------------------------------------
extern "C" void kernel_launch(void* const* d_in, const int* in_sizes, int n_in,
                              void* d_out, int out_size) {
    const int*   coords = (const int*)  d_in[0];
    const float* feats  = (const float*)d_in[1];
    const float* w1     = (const float*)d_in[2];
    const float* g1     = (const float*)d_in[3];
    const float* b1     = (const float*)d_in[4];
    const float* w3     = (const float*)d_in[5];
    const float* g2     = (const float*)d_in[6];
    const float* b2     = (const float*)d_in[7];
    const float* w_out  = (const float*)d_in[8];
    float* out = (float*)d_out;

    cudaFuncSetAttribute(k_conv, cudaFuncAttributeMaxDynamicSharedMemorySize, CONV_SMEM);

    k_init    <<<TABSZ / 256, 256>>>();
    k_build   <<<NPTS / 256, 256>>>(coords);
    k_offinit <<<1, 512>>>();
    k_wprep   <<<27 * HDIM * HDIM / 1024, 256>>>(w3);
    k_knng    <<<NPTS / 256, 256>>>(coords);
    k_gemm1   <<<NPTS / 32, 128>>>(feats, w1);
    k_bnfin   <<<1, 128>>>(g1, b1, 0, 1024);
    k_happly  <<<NPTS * 32 / 256, 256>>>();
    k_conv    <<<NPTS / 128, 256, CONV_SMEM>>>(coords);
    k_bnstats2<<<256, 128>>>();
    k_bnfin   <<<1, 128>>>(g2, b2, 1, 256);
    k_final   <<<NPTS / 16, 256>>>(w_out, out);
}

// round 17
// speedup vs baseline: 5.3202x; 1.3171x over previous
#include <cuda_runtime.h>
#include <cuda_fp16.h>
#include <cstdint>

#define NPTS   32768
#define NBATCH 4
#define MPER   8192
#define KNN    8
#define HDIM   128
#define COMB   72
#define TABSZ  (4*64*64*64)

// ---------------- scratch ----------------------------------------------------
__device__ int     g_table[TABSZ];
__device__ int2    g_soff[343];           // (key-offset, d2) sorted by d2
__device__ int     g_nbr[NPTS * KNN];
__device__ float   g_pre1[NPTS * HDIM];
__device__ __half  g_h[NPTS * HDIM];              // fp16 BN1 output
__device__ __half  g_w3h[108 * 128 * 32];         // w3 transposed [o*4+kc][n][k32], fp16
__device__ float   g_pre2[NPTS * HDIM];
#define SQOFF (1024 * HDIM)
__device__ float   g_part[2 * 1024 * HDIM];
__device__ float   g_stats1[2 * HDIM];
__device__ float   g_stats2[2 * HDIM];

// ---------------- helpers ----------------------------------------------------
__device__ __forceinline__ void hmma16816(float* c, const unsigned* a,
                                          unsigned b0, unsigned b1) {
    asm volatile(
        "mma.sync.aligned.m16n8k16.row.col.f32.f16.f16.f32 "
        "{%0,%1,%2,%3},{%4,%5,%6,%7},{%8,%9},{%0,%1,%2,%3};"
        : "+f"(c[0]), "+f"(c[1]), "+f"(c[2]), "+f"(c[3])
        : "r"(a[0]), "r"(a[1]), "r"(a[2]), "r"(a[3]), "r"(b0), "r"(b1));
}
__device__ __forceinline__ void cp8(void* dst, const void* src, int bytes) {
    unsigned d = (unsigned)__cvta_generic_to_shared(dst);
    asm volatile("cp.async.ca.shared.global [%0], [%1], 8, %2;"
                 :: "r"(d), "l"(src), "r"(bytes));
}
__device__ __forceinline__ void cp_commit() {
    asm volatile("cp.async.commit_group;");
}
template <int N> __device__ __forceinline__ void cp_wait() {
    asm volatile("cp.async.wait_group %0;" :: "n"(N));
}

// ---------------- table -------------------------------------------------------
__global__ void k_init() { g_table[blockIdx.x * 256 + threadIdx.x] = -1; }

__global__ void k_build(const int* __restrict__ coords) {
    int n = blockIdx.x * 256 + threadIdx.x;
    int4 c = ((const int4*)coords)[n];
    g_table[((c.x * 64 + c.y + 1) * 64 + (c.z + 1)) * 64 + (c.w + 1)] = n;
}

// ---------------- sorted offset list (7^3 cube, ascending d2) ----------------
__global__ void k_offinit() {
    __shared__ int d2s[343];
    int t = threadIdx.x;
    if (t < 343) {
        int ox = t / 49 - 3, oy = (t / 7) % 7 - 3, oz = t % 7 - 3;
        d2s[t] = ox * ox + oy * oy + oz * oz;
    }
    __syncthreads();
    if (t < 343) {
        int ox = t / 49 - 3, oy = (t / 7) % 7 - 3, oz = t % 7 - 3;
        int d2 = d2s[t];
        int rank = 0;
        for (int j = 0; j < 343; j++) {
            int dj = d2s[j];
            rank += (dj < d2) || (dj == d2 && j < t);
        }
        g_soff[rank] = make_int2(ox * 4096 + oy * 64 + oz, d2);
    }
}

// ---------------- grid-shell exact kNN ---------------------------------------
__global__ void k_knng(const int* __restrict__ coords) {
    __shared__ int2 soff[343];
    for (int i = threadIdx.x; i < 343; i += 256) soff[i] = g_soff[i];
    __syncthreads();

    int n = blockIdx.x * 256 + threadIdx.x;
    int4 c = ((const int4*)coords)[n];
    int qkey = ((c.x * 64 + c.y + 1) * 64 + (c.z + 1)) * 64 + (c.w + 1);

    unsigned best[8];
#pragma unroll
    for (int s = 0; s < 8; s++) best[s] = 0xFFFFFFFFu;

    auto insert = [&](unsigned key) {
        if (key < best[7]) {
#pragma unroll
            for (int s = 0; s < 8; s++) {
                unsigned mx = key > best[s] ? key : best[s];
                best[s]     = key < best[s] ? key : best[s];
                key = mx;
            }
        }
    };

    int2 od = soff[0];
    int key0 = qkey + od.x;
    int jcur = (key0 >= 0) ? g_table[key0] : -1;
    for (int it = 0; it < 343; it++) {
        int2 odn = soff[(it + 1 < 343) ? it + 1 : it];
        int keyn = qkey + odn.x;
        int jn = (keyn >= 0) ? g_table[keyn] : -1;
        if ((unsigned)od.y > (best[7] >> 13)) break;
        if (jcur >= 0)
            insert((unsigned)od.y * 8192u + (unsigned)(jcur & 8191));
        od = odn; jcur = jn;
    }

    for (int R = 4; R <= 31; R++) {
        if ((best[7] >> 13) < (unsigned)(R * R)) break;
        for (int ox = -R; ox <= R; ox++) {
            for (int oy = -R; oy <= R; oy++) {
                bool face = (ox == -R || ox == R || oy == -R || oy == R);
                int zstep = face ? 1 : 2 * R;
                for (int oz = -R; oz <= R; oz += zstep) {
                    int key = qkey + ox * 4096 + oy * 64 + oz;
                    if (key < 0) continue;
                    int j = g_table[key];
                    if (j >= 0) {
                        int d2 = ox * ox + oy * oy + oz * oz;
                        insert((unsigned)d2 * 8192u + (unsigned)(j & 8191));
                    }
                }
            }
        }
    }

    int base = (n >> 13) << 13;
#pragma unroll
    for (int s = 0; s < 8; s++)
        g_nbr[(size_t)n * 8 + s] = base + (int)(best[s] & 0x1FFFu);
}

// ---------------- GEMM1 + fused BN1 partial stats ----------------------------
__global__ void k_gemm1(const float* __restrict__ feats, const float* __restrict__ w1) {
    __shared__ float c_s[32 * COMB];
    int base = blockIdx.x * 32;
    int ch = threadIdx.x;
    for (int idx = threadIdx.x; idx < 32 * 9; idx += 128) {
        int p = idx / 9, slot = idx - p * 9;
        int src = (slot == 0) ? (base + p) : g_nbr[(base + p) * 8 + slot - 1];
        const float4* s4 = (const float4*)(feats + (size_t)src * 8);
        float4* dst = (float4*)&c_s[p * COMB + slot * 8];
        dst[0] = s4[0]; dst[1] = s4[1];
    }
    float wreg[COMB];
#pragma unroll
    for (int k = 0; k < COMB; k++) wreg[k] = w1[k * HDIM + ch];
    __syncthreads();

    float s = 0.f, q = 0.f;
    for (int p = 0; p < 32; p++) {
        const float4* cp = (const float4*)(c_s + p * COMB);
        float acc = 0.f;
#pragma unroll
        for (int k4 = 0; k4 < COMB / 4; k4++) {
            float4 cv = cp[k4];
            acc += cv.x * wreg[k4 * 4]     + cv.y * wreg[k4 * 4 + 1]
                 + cv.z * wreg[k4 * 4 + 2] + cv.w * wreg[k4 * 4 + 3];
        }
        g_pre1[(size_t)(base + p) * HDIM + ch] = acc;
        s += acc; q += acc * acc;
    }
    g_part[blockIdx.x * HDIM + ch] = s;
    g_part[SQOFF + blockIdx.x * HDIM + ch] = q;
}

// ---------------- BN partials for pre2 ---------------------------------------
__global__ void k_bnstats2() {
    int ch = threadIdx.x;
    float s = 0.f, q = 0.f;
    const float* p = g_pre2 + (size_t)blockIdx.x * 128 * HDIM + ch;
#pragma unroll 4
    for (int r = 0; r < 128; r++) {
        float v = p[r * HDIM];
        s += v; q += v * v;
    }
    g_part[blockIdx.x * HDIM + ch] = s;
    g_part[SQOFF + blockIdx.x * HDIM + ch] = q;
}

__global__ void k_bnfin(const float* __restrict__ gamma, const float* __restrict__ beta,
                        int which, int npart) {
    int ch = threadIdx.x;
    float s = 0.f, q = 0.f;
#pragma unroll 8
    for (int i = 0; i < npart; i++) {
        s += g_part[i * HDIM + ch];
        q += g_part[SQOFF + i * HDIM + ch];
    }
    float mu  = s * (1.f / NPTS);
    float var = q * (1.f / NPTS) - mu * mu;
    float sc  = rsqrtf(var + 1e-5f) * gamma[ch];
    float* st = which ? g_stats2 : g_stats1;
    st[ch]        = sc;
    st[HDIM + ch] = beta[ch] - mu * sc;
}

// ---------------- apply BN1 + ReLU -> h (fp16) --------------------------------
__global__ void k_happly() {
    int i = blockIdx.x * 256 + threadIdx.x;       // float4 units: NPTS*32
    float4 v = ((const float4*)g_pre1)[i];
    int c = (i & 31) << 2;
    float4 u;
    u.x = fmaxf(v.x * g_stats1[c]     + g_stats1[HDIM + c],     0.f);
    u.y = fmaxf(v.y * g_stats1[c + 1] + g_stats1[HDIM + c + 1], 0.f);
    u.z = fmaxf(v.z * g_stats1[c + 2] + g_stats1[HDIM + c + 2], 0.f);
    u.w = fmaxf(v.w * g_stats1[c + 3] + g_stats1[HDIM + c + 3], 0.f);
    __half2 h01 = __floats2half2_rn(u.x, u.y);
    __half2 h23 = __floats2half2_rn(u.z, u.w);
    ((__half2*)g_h)[i * 2]     = h01;
    ((__half2*)g_h)[i * 2 + 1] = h23;
}

// ---------------- w3 -> transposed fp16 chunk tiles ---------------------------
// tile t = o*4+kc holds B[n=0..127][k32=0..31] = w3[o][kc*32+k32][n], fp16
__global__ void k_wprep(const float* __restrict__ w3) {
    int i = blockIdx.x * 256 + threadIdx.x;   // 27*128*128 elements
    int o = i >> 14;
    int r = i & 16383;
    int k = r >> 7;          // input channel (K)
    int n = r & 127;         // output channel (N)
    int tile = o * 4 + (k >> 5);
    g_w3h[tile * 4096 + n * 32 + (k & 31)] = __float2half_rn(w3[i]);
}

// ---------------- sparse conv: pipelined fp16 mma.sync GEMM ------------------
// M=128 pts x N=128 ch, K=3456 in 108 chunks of 32; 3-stage cp.async pipeline.
// smem rows: 32 fp16 = 64B data, stride 80B (20 words): banks (4*gid+tig) CF.
#define ROWB   80
#define TILEB  (128 * ROWB)             // 10240 B per tile
#define NCHUNK 108
#define CONV_SMEM (6 * TILEB + 27 * 128 * 4)

__global__ void __launch_bounds__(256, 2)
k_conv(const int* __restrict__ coords) {
    extern __shared__ char sm[];
    char* A0  = sm;                         // 3 A stages
    char* B0  = sm + 3 * TILEB;             // 3 B stages
    int*  j_s = (int*)(sm + 6 * TILEB);     // 27*128
    int base = blockIdx.x * 128;
    int tid  = threadIdx.x;

    for (int idx = tid; idx < 27 * 128; idx += 256) {
        int o = idx >> 7, p = idx & 127;
        int4 c = ((const int4*)coords)[base + p];
        int ox = o / 9 - 1, oy = (o / 3) % 3 - 1, oz = o % 3 - 1;
        int key = ((c.x * 64 + c.y + 1 + ox) * 64 + (c.z + 1 + oy)) * 64 + (c.w + 1 + oz);
        j_s[idx] = g_table[key];
    }
    __syncthreads();

    auto load_chunk = [&](int c, int s) {
        int o = c >> 2, kin = (c & 3) * 32;     // halfword offset in g_h row
        char* As = A0 + s * TILEB;
        char* Bs = B0 + s * TILEB;
#pragma unroll
        for (int qq = 0; qq < 4; qq++) {
            int idx = tid + qq * 256;            // 0..1023
            int p = idx >> 3, part = idx & 7;
            int j = j_s[(o << 7) + p];
            int sz = (j >= 0) ? 8 : 0;
            int jc = j >= 0 ? j : 0;
            cp8(As + p * ROWB + part * 8,
                g_h + (size_t)jc * HDIM + kin + part * 4, sz);
        }
        const __half* wsrc = g_w3h + (size_t)c * 4096;
#pragma unroll
        for (int qq = 0; qq < 4; qq++) {
            int idx = tid + qq * 256;
            int p = idx >> 3, part = idx & 7;
            cp8(Bs + p * ROWB + part * 8, wsrc + p * 32 + part * 4, 8);
        }
        cp_commit();
    };

    int lane = tid & 31, warp = tid >> 5;
    int gid = lane >> 2, tig = lane & 3;
    int mgrp = warp >> 1;                    // 0..3 : 32-point group
    int ngrp = warp & 1;                     // 0..1 : 64-chan group

    float acc[2][8][4];
#pragma unroll
    for (int mt = 0; mt < 2; mt++)
#pragma unroll
        for (int nt = 0; nt < 8; nt++)
#pragma unroll
            for (int r = 0; r < 4; r++) acc[mt][nt][r] = 0.f;

    load_chunk(0, 0);
    load_chunk(1, 1);

    for (int c = 0; c < NCHUNK; c++) {
        if (c + 2 < NCHUNK) load_chunk(c + 2, (c + 2) % 3);
        cp_wait<1>();
        __syncthreads();
        const unsigned* As = (const unsigned*)(A0 + (c % 3) * TILEB);
        const unsigned* Bs = (const unsigned*)(B0 + (c % 3) * TILEB);
#pragma unroll
        for (int ks = 0; ks < 2; ks++) {
            int kw = ks * 8;                 // word offset (16 fp16 per kstep)
            unsigned a[2][4];
#pragma unroll
            for (int mt = 0; mt < 2; mt++) {
                int pr = mgrp * 32 + mt * 16;
                a[mt][0] = As[(pr + gid) * 20 + kw + tig];
                a[mt][1] = As[(pr + gid + 8) * 20 + kw + tig];
                a[mt][2] = As[(pr + gid) * 20 + kw + tig + 4];
                a[mt][3] = As[(pr + gid + 8) * 20 + kw + tig + 4];
            }
#pragma unroll
            for (int nt = 0; nt < 8; nt++) {
                int nc = ngrp * 64 + nt * 8;
                unsigned b0 = Bs[(nc + gid) * 20 + kw + tig];
                unsigned b1 = Bs[(nc + gid) * 20 + kw + tig + 4];
                hmma16816(acc[0][nt], a[0], b0, b1);
                hmma16816(acc[1][nt], a[1], b0, b1);
            }
        }
        __syncthreads();
    }

#pragma unroll
    for (int mt = 0; mt < 2; mt++) {
#pragma unroll
        for (int nt = 0; nt < 8; nt++) {
            int row0 = base + mgrp * 32 + mt * 16 + gid;
            int col  = ngrp * 64 + nt * 8 + tig * 2;
            *(float2*)&g_pre2[(size_t)row0 * HDIM + col] =
                make_float2(acc[mt][nt][0], acc[mt][nt][1]);
            *(float2*)&g_pre2[(size_t)(row0 + 8) * HDIM + col] =
                make_float2(acc[mt][nt][2], acc[mt][nt][3]);
        }
    }
}

// ---------------- final -------------------------------------------------------
__global__ void k_final(const float* __restrict__ w_out, float* __restrict__ out) {
    __shared__ float h_s[16 * HDIM];
    __shared__ float w_s[HDIM * 16];
    int base = blockIdx.x * 16;
    for (int i = threadIdx.x; i < HDIM * 16; i += 256) w_s[i] = w_out[i];
    for (int i = threadIdx.x; i < 16 * HDIM; i += 256) {
        int ch = i & 127;
        float v = g_pre2[(size_t)base * HDIM + i];
        v = v * g_stats2[ch] + g_stats2[HDIM + ch];
        h_s[i] = fmaxf(v, 0.f);
    }
    __syncthreads();
    int p = threadIdx.x >> 4, oc = threadIdx.x & 15;
    float acc = 0.f;
#pragma unroll 8
    for (int k = 0; k < HDIM; k++)
        acc += h_s[p * HDIM + k] * w_s[k * 16 + oc];
    out[(size_t)(base + p) * 16 + oc] = acc;
}

// ---------------- launcher ----------------------------------------------------
extern "C" void kernel_launch(void* const* d_in, const int* in_sizes, int n_in,
                              void* d_out, int out_size) {
    const int*   coords = (const int*)  d_in[0];
    const float* feats  = (const float*)d_in[1];
    const float* w1     = (const float*)d_in[2];
    const float* g1     = (const float*)d_in[3];
    const float* b1     = (const float*)d_in[4];
    const float* w3     = (const float*)d_in[5];
    const float* g2     = (const float*)d_in[6];
    const float* b2     = (const float*)d_in[7];
    const float* w_out  = (const float*)d_in[8];
    float* out = (float*)d_out;

    cudaFuncSetAttribute(k_conv, cudaFuncAttributeMaxDynamicSharedMemorySize, CONV_SMEM);

    k_init    <<<TABSZ / 256, 256>>>();
    k_build   <<<NPTS / 256, 256>>>(coords);
    k_offinit <<<1, 512>>>();
    k_wprep   <<<27 * HDIM * HDIM / 256, 256>>>(w3);
    k_knng    <<<NPTS / 256, 256>>>(coords);
    k_gemm1   <<<NPTS / 32, 128>>>(feats, w1);
    k_bnfin   <<<1, 128>>>(g1, b1, 0, 1024);
    k_happly  <<<NPTS * 32 / 256, 256>>>();
    k_conv    <<<NPTS / 128, 256, CONV_SMEM>>>(coords);
    k_bnstats2<<<256, 128>>>();
    k_bnfin   <<<1, 128>>>(g2, b2, 1, 256);
    k_final   <<<NPTS / 16, 256>>>(w_out, out);
}